// round 6
// baseline (speedup 1.0000x reference)
#include <cuda_runtime.h>
#include <cstdint>

// ---------------- problem constants ----------------
#define TOKENS 4096
#define IN_F   4096
#define OUT_F  11008
#define NGRP   32

// ---------------- tile config ----------------
#define BM 128
#define BN 128
#define BK 32
#define NITER (IN_F / BK)       // 128
#define STAGES 3
#define STAGE_FLOATS 4096       // 16KB per operand per stage
#define TILE_FLOATS (128 * STAGE_FLOATS)
#define NTHREADS 128

// ---------------- persistent scratch ----------------
__device__ float g_xs[(size_t)TOKENS * IN_F];     // x, tf32, fragment-tiled
__device__ float g_wd[(size_t)OUT_F * IN_F];      // W, dequant tf32, fragment-tiled

__device__ __forceinline__ uint32_t tf32r(float f) {
    uint32_t r; asm("cvt.rna.tf32.f32 %0, %1;" : "=r"(r) : "f"(f)); return r;
}
__device__ __forceinline__ float tf32f(float f) { return __uint_as_float(tf32r(f)); }

__device__ __forceinline__ uint32_t smem_u32(const void* p) {
    uint32_t a;
    asm("{ .reg .u64 t; cvta.to.shared.u64 t, %1; cvt.u32.u64 %0, t; }" : "=r"(a) : "l"(p));
    return a;
}
__device__ __forceinline__ void cp16(uint32_t dst, const void* src) {
    asm volatile("cp.async.cg.shared.global [%0], [%1], 16;" :: "r"(dst), "l"(src) : "memory");
}
__device__ __forceinline__ void cp_commit() { asm volatile("cp.async.commit_group;" ::: "memory"); }
__device__ __forceinline__ void cp_wait1()  { asm volatile("cp.async.wait_group 1;" ::: "memory"); }

__device__ __forceinline__ void mma8(float& d0, float& d1, float& d2, float& d3,
                                     uint32_t a0, uint32_t a1, uint32_t a2, uint32_t a3,
                                     uint32_t b0, uint32_t b1) {
    asm volatile("mma.sync.aligned.m16n8k8.row.col.f32.tf32.tf32.f32 "
                 "{%0,%1,%2,%3}, {%4,%5,%6,%7}, {%8,%9}, {%0,%1,%2,%3};"
                 : "+f"(d0), "+f"(d1), "+f"(d2), "+f"(d3)
                 : "r"(a0), "r"(a1), "r"(a2), "r"(a3), "r"(b0), "r"(b1));
}

// ============ prepass 1: x -> tf32, A-fragment-register-contiguous tiling ============
// Stage (mt,kst) = 4096 floats = 32 blocks (blk = ks*8 + mb) of 128.
// Within block: addr = lane*4 + reg;  lane = (m&7)*4 + (k&3);
// reg: 0=(m,k) 1=(m+8,k) 2=(m,k+4) 3=(m+8,k+4).
__global__ void __launch_bounds__(256)
prep_x_kernel(const float* __restrict__ x)
{
    const int gid  = blockIdx.x * 256 + threadIdx.x;
    const int lane = gid & 31;
    const int blk  = (gid >> 5) & 31;
    const int stg  = gid >> 10;            // mt*128 + kst
    const int kst  = stg & 127;
    const int mt   = stg >> 7;
    const int ks = blk >> 3, mb = blk & 7;
    const int m = mt * 128 + mb * 16 + (lane >> 2);
    const int k = kst * 32 + ks * 8 + (lane & 3);
    const float* xr = x + (size_t)m * IN_F + k;
    float4 o;
    o.x = tf32f(xr[0]);
    o.y = tf32f(xr[(size_t)8 * IN_F]);
    o.z = tf32f(xr[4]);
    o.w = tf32f(xr[(size_t)8 * IN_F + 4]);
    *(float4*)(g_xs + (size_t)stg * STAGE_FLOATS + blk * 128 + lane * 4) = o;
}

// ============ prepass 2: W -> dequant tf32, B-fragment pair tiling ============
// Stage (nt,kst) = 32 blocks (blk = ks*8 + np, np = n-pair of 16) of 128.
// Within block: addr = lane*4 + c;  lane = (n&7)*4 + (k&3);
// c: 0=(n,k) 1=(n,k+4) 2=(n+8,k) 3=(n+8,k+4).
__global__ void __launch_bounds__(256)
prep_w_kernel(const int*   __restrict__ wp,
              const float* __restrict__ ws,
              const int*   __restrict__ wz)
{
    const int gid  = blockIdx.x * 256 + threadIdx.x;
    const int lane = gid & 31;
    const int blk  = (gid >> 5) & 31;
    const int stg  = gid >> 10;            // nt*128 + kst
    const int kst  = stg & 127;
    const int nt   = stg >> 7;
    const int ks = blk >> 3, np = blk & 7;
    const int n = nt * 128 + np * 16 + (lane >> 2);
    const int k = kst * 32 + ks * 8 + (lane & 3);
    const int grp = k >> 7;                // k and k+4 always in same group

    const int* r0 = wp + (size_t)n * 2048;         // one packed byte per int
    const int* r1 = r0 + (size_t)8 * 2048;
    const int sh = (k & 1) * 4;
    const int i0 = k >> 1;
    const int b00 = r0[i0], b01 = r0[i0 + 2];
    const int b10 = r1[i0], b11 = r1[i0 + 2];

    const float s0 = ws[(size_t)n * NGRP + grp];
    const float c0 = (-8.0f - (float)wz[(size_t)n * NGRP + grp]) * s0;
    const float s1 = ws[(size_t)(n + 8) * NGRP + grp];
    const float c1 = (-8.0f - (float)wz[(size_t)(n + 8) * NGRP + grp]) * s1;

    float4 o;
    o.x = tf32f(fmaf((float)(int)((((uint32_t)b00 >> sh) & 15u) ^ 8u), s0, c0));
    o.y = tf32f(fmaf((float)(int)((((uint32_t)b01 >> sh) & 15u) ^ 8u), s0, c0));
    o.z = tf32f(fmaf((float)(int)((((uint32_t)b10 >> sh) & 15u) ^ 8u), s1, c1));
    o.w = tf32f(fmaf((float)(int)((((uint32_t)b11 >> sh) & 15u) ^ 8u), s1, c1));
    *(float4*)(g_wd + (size_t)stg * STAGE_FLOATS + blk * 128 + lane * 4) = o;
}

// ============ main GEMM: 64x64 warp tiles, all-LDS.128, cp.async pipeline ============
#define SMEM_BYTES (2 * STAGES * STAGE_FLOATS * 4)   // 98304

__global__ void __launch_bounds__(NTHREADS, 2)
gemm_kernel(float* __restrict__ y)
{
    extern __shared__ float sm[];   // [STAGES][4096] A then [STAGES][4096] B

    const int tid  = threadIdx.x;
    const int lane = tid & 31;
    const int wid  = tid >> 5;
    const int warprow = wid >> 1;       // 0..1 (64 m)
    const int warpcol = wid & 1;        // 0..1 (64 n)
    const int mt = blockIdx.x;          // m fastest: one n-tile's CTAs co-resident
    const int nt = blockIdx.y;

    const float* Asrc = g_xs + (size_t)mt * TILE_FLOATS + tid * 32;
    const float* Bsrc = g_wd + (size_t)nt * TILE_FLOATS + tid * 32;
    const uint32_t smA = smem_u32(sm) + tid * 128;
    const uint32_t smB = smA + STAGES * STAGE_FLOATS * 4;

    #pragma unroll
    for (int i = 0; i < STAGES - 1; i++) {
        #pragma unroll
        for (int j = 0; j < 8; j++) {
            cp16(smA + i * (STAGE_FLOATS * 4) + j * 16, Asrc + (size_t)i * STAGE_FLOATS + j * 4);
            cp16(smB + i * (STAGE_FLOATS * 4) + j * 16, Bsrc + (size_t)i * STAGE_FLOATS + j * 4);
        }
        cp_commit();
    }

    float acc[4][8][4];
    #pragma unroll
    for (int mf = 0; mf < 4; mf++)
        #pragma unroll
        for (int f = 0; f < 8; f++)
            #pragma unroll
            for (int q = 0; q < 4; q++) acc[mf][f][q] = 0.0f;

    int st = 0, fs = STAGES - 1;
    for (int i = 0; i < NITER; i++) {
        cp_wait1();
        __syncthreads();

        if (i + STAGES - 1 < NITER) {
            #pragma unroll
            for (int j = 0; j < 8; j++) {
                cp16(smA + fs * (STAGE_FLOATS * 4) + j * 16,
                     Asrc + (size_t)(i + STAGES - 1) * STAGE_FLOATS + j * 4);
                cp16(smB + fs * (STAGE_FLOATS * 4) + j * 16,
                     Bsrc + (size_t)(i + STAGES - 1) * STAGE_FLOATS + j * 4);
            }
        }
        cp_commit();

        const float* As = sm + st * STAGE_FLOATS;
        const float* Bs = sm + STAGES * STAGE_FLOATS + st * STAGE_FLOATS;

        #pragma unroll
        for (int ks = 0; ks < 4; ks++) {
            float4 av[4];
            #pragma unroll
            for (int mf = 0; mf < 4; mf++)
                av[mf] = *(const float4*)&As[(ks * 8 + warprow * 4 + mf) * 128 + lane * 4];
            float4 bv[4];
            #pragma unroll
            for (int fp = 0; fp < 4; fp++)
                bv[fp] = *(const float4*)&Bs[(ks * 8 + warpcol * 4 + fp) * 128 + lane * 4];

            #pragma unroll
            for (int mf = 0; mf < 4; mf++) {
                const uint32_t a0 = __float_as_uint(av[mf].x), a1 = __float_as_uint(av[mf].y);
                const uint32_t a2 = __float_as_uint(av[mf].z), a3 = __float_as_uint(av[mf].w);
                #pragma unroll
                for (int fp = 0; fp < 4; fp++) {
                    mma8(acc[mf][2*fp][0], acc[mf][2*fp][1], acc[mf][2*fp][2], acc[mf][2*fp][3],
                         a0, a1, a2, a3,
                         __float_as_uint(bv[fp].x), __float_as_uint(bv[fp].y));
                    mma8(acc[mf][2*fp+1][0], acc[mf][2*fp+1][1], acc[mf][2*fp+1][2], acc[mf][2*fp+1][3],
                         a0, a1, a2, a3,
                         __float_as_uint(bv[fp].z), __float_as_uint(bv[fp].w));
                }
            }
        }

        st = (st + 1 == STAGES) ? 0 : st + 1;
        fs = (fs + 1 == STAGES) ? 0 : fs + 1;
    }

    // ---- epilogue ----
    const int g = lane >> 2, t = lane & 3;
    const int m0 = mt * BM, n0 = nt * BN;
    #pragma unroll
    for (int mf = 0; mf < 4; mf++) {
        const int row0 = m0 + warprow * 64 + mf * 16 + g;
        #pragma unroll
        for (int f = 0; f < 8; f++) {
            float* p0 = y + (size_t)row0 * OUT_F + n0 + warpcol * 64 + f * 8 + 2 * t;
            float* p1 = p0 + (size_t)8 * OUT_F;
            *(float2*)p0 = make_float2(acc[mf][f][0], acc[mf][f][1]);
            *(float2*)p1 = make_float2(acc[mf][f][2], acc[mf][f][3]);
        }
    }
}

extern "C" void kernel_launch(void* const* d_in, const int* in_sizes, int n_in,
                              void* d_out, int out_size)
{
    const float* x  = (const float*)d_in[0];
    const int*   wp = (const int*)d_in[1];
    const float* ws = (const float*)d_in[2];
    const int*   wz = (const int*)d_in[3];
    float*       y  = (float*)d_out;

    static bool attr_set = false;
    if (!attr_set) {
        cudaFuncSetAttribute(gemm_kernel,
                             cudaFuncAttributeMaxDynamicSharedMemorySize, SMEM_BYTES);
        attr_set = true;
    }

    prep_x_kernel<<<(TOKENS * (IN_F / 4)) / 256, 256>>>(x);
    prep_w_kernel<<<(OUT_F * (IN_F / 4)) / 256, 256>>>(wp, ws, wz);
    gemm_kernel<<<dim3(TOKENS / BM, OUT_F / BN), NTHREADS, SMEM_BYTES>>>(y);
}

// round 7
// speedup vs baseline: 1.5522x; 1.5522x over previous
#include <cuda_runtime.h>
#include <cstdint>

// ---------------- problem constants ----------------
#define TOKENS 4096
#define IN_F   4096
#define OUT_F  11008
#define NGRP   32

// ---------------- tile config ----------------
#define BM 128
#define BN 128
#define BK 32
#define NITER (IN_F / BK)       // 128
#define STAGES 3
#define STAGE_FLOATS 4096       // 16KB per operand per stage
#define TILE_FLOATS (128 * STAGE_FLOATS)
#define NTHREADS 256

// ---------------- persistent scratch ----------------
__device__ float g_xs[(size_t)TOKENS * IN_F];     // x, tf32, fragment-tiled
__device__ float g_wd[(size_t)OUT_F * IN_F];      // W, dequant tf32, fragment-tiled

__device__ __forceinline__ uint32_t tf32r(float f) {
    uint32_t r; asm("cvt.rna.tf32.f32 %0, %1;" : "=r"(r) : "f"(f)); return r;
}
__device__ __forceinline__ float tf32f(float f) { return __uint_as_float(tf32r(f)); }

__device__ __forceinline__ uint32_t smem_u32(const void* p) {
    uint32_t a;
    asm("{ .reg .u64 t; cvta.to.shared.u64 t, %1; cvt.u32.u64 %0, t; }" : "=r"(a) : "l"(p));
    return a;
}
__device__ __forceinline__ void cp16(uint32_t dst, const void* src) {
    asm volatile("cp.async.cg.shared.global [%0], [%1], 16;" :: "r"(dst), "l"(src) : "memory");
}
__device__ __forceinline__ void cp_commit() { asm volatile("cp.async.commit_group;" ::: "memory"); }
__device__ __forceinline__ void cp_wait1()  { asm volatile("cp.async.wait_group 1;" ::: "memory"); }

__device__ __forceinline__ void mma8(float& d0, float& d1, float& d2, float& d3,
                                     uint32_t a0, uint32_t a1, uint32_t a2, uint32_t a3,
                                     uint32_t b0, uint32_t b1) {
    asm volatile("mma.sync.aligned.m16n8k8.row.col.f32.tf32.tf32.f32 "
                 "{%0,%1,%2,%3}, {%4,%5,%6,%7}, {%8,%9}, {%0,%1,%2,%3};"
                 : "+f"(d0), "+f"(d1), "+f"(d2), "+f"(d3)
                 : "r"(a0), "r"(a1), "r"(a2), "r"(a3), "r"(b0), "r"(b1));
}

// ============ prepass 1: x -> tf32, A-fragment-register-contiguous tiling ============
// Stage (mt,kst) = 32 blocks (blk = ks*8 + mb) of 128 floats.
// Within block: addr = lane*4 + reg; lane = (m&7)*4 + (k&3);
// reg: 0=(m,k) 1=(m+8,k) 2=(m,k+4) 3=(m+8,k+4).
__global__ void __launch_bounds__(256)
prep_x_kernel(const float* __restrict__ x)
{
    const int gid  = blockIdx.x * 256 + threadIdx.x;
    const int lane = gid & 31;
    const int blk  = (gid >> 5) & 31;
    const int stg  = gid >> 10;            // mt*128 + kst
    const int kst  = stg & 127;
    const int mt   = stg >> 7;
    const int ks = blk >> 3, mb = blk & 7;
    const int m = mt * 128 + mb * 16 + (lane >> 2);
    const int k = kst * 32 + ks * 8 + (lane & 3);
    const float* xr = x + (size_t)m * IN_F + k;
    float4 o;
    o.x = tf32f(xr[0]);
    o.y = tf32f(xr[(size_t)8 * IN_F]);
    o.z = tf32f(xr[4]);
    o.w = tf32f(xr[(size_t)8 * IN_F + 4]);
    *(float4*)(g_xs + (size_t)stg * STAGE_FLOATS + blk * 128 + lane * 4) = o;
}

// ============ prepass 2: W -> dequant tf32, B-fragment n-pair tiling ============
// Stage (nt,kst) = 32 blocks (blk = ks*8 + np; np = pair of 16 n) of 128 floats.
// Within block: addr = lane*4 + c; lane = (n&7)*4 + (k&3);
// c: 0=(n,k) 1=(n,k+4) 2=(n+8,k) 3=(n+8,k+4).
__global__ void __launch_bounds__(256)
prep_w_kernel(const int*   __restrict__ wp,
              const float* __restrict__ ws,
              const int*   __restrict__ wz)
{
    const int gid  = blockIdx.x * 256 + threadIdx.x;
    const int lane = gid & 31;
    const int blk  = (gid >> 5) & 31;
    const int stg  = gid >> 10;            // nt*128 + kst
    const int kst  = stg & 127;
    const int nt   = stg >> 7;
    const int ks = blk >> 3, np = blk & 7;
    const int n = nt * 128 + np * 16 + (lane >> 2);
    const int k = kst * 32 + ks * 8 + (lane & 3);
    const int grp = k >> 7;

    const int* r0 = wp + (size_t)n * 2048;   // one packed byte per int32
    const int* r1 = r0 + (size_t)8 * 2048;
    const int sh = (k & 1) * 4;
    const int i0 = k >> 1;
    const int b00 = r0[i0], b01 = r0[i0 + 2];
    const int b10 = r1[i0], b11 = r1[i0 + 2];

    const float s0 = ws[(size_t)n * NGRP + grp];
    const float c0 = (-8.0f - (float)wz[(size_t)n * NGRP + grp]) * s0;
    const float s1 = ws[(size_t)(n + 8) * NGRP + grp];
    const float c1 = (-8.0f - (float)wz[(size_t)(n + 8) * NGRP + grp]) * s1;

    float4 o;
    o.x = tf32f(fmaf((float)(int)((((uint32_t)b00 >> sh) & 15u) ^ 8u), s0, c0));
    o.y = tf32f(fmaf((float)(int)((((uint32_t)b01 >> sh) & 15u) ^ 8u), s0, c0));
    o.z = tf32f(fmaf((float)(int)((((uint32_t)b10 >> sh) & 15u) ^ 8u), s1, c1));
    o.w = tf32f(fmaf((float)(int)((((uint32_t)b11 >> sh) & 15u) ^ 8u), s1, c1));
    *(float4*)(g_wd + (size_t)stg * STAGE_FLOATS + blk * 128 + lane * 4) = o;
}

// ============ main GEMM: 64x32 warp tiles (R5 shape), LDS.128 fragments ============
#define SMEM_BYTES (2 * STAGES * STAGE_FLOATS * 4)   // 98304

__global__ void __launch_bounds__(NTHREADS, 2)
gemm_kernel(float* __restrict__ y)
{
    extern __shared__ float sm[];   // [STAGES][4096] A then [STAGES][4096] B

    const int tid  = threadIdx.x;
    const int lane = tid & 31;
    const int wid  = tid >> 5;
    const int warprow = wid >> 2;       // 0..1  (64 m)
    const int warpcol = wid & 3;        // 0..3  (32 n)
    const int mt = blockIdx.x;          // m fastest: co-resident CTAs share nt
    const int nt = blockIdx.y;

    const float* Asrc = g_xs + (size_t)mt * TILE_FLOATS + tid * 16;
    const float* Bsrc = g_wd + (size_t)nt * TILE_FLOATS + tid * 16;
    const uint32_t smA = smem_u32(sm) + tid * 64;
    const uint32_t smB = smA + STAGES * STAGE_FLOATS * 4;

    #pragma unroll
    for (int i = 0; i < STAGES - 1; i++) {
        #pragma unroll
        for (int j = 0; j < 4; j++) {
            cp16(smA + i * (STAGE_FLOATS * 4) + j * 16, Asrc + (size_t)i * STAGE_FLOATS + j * 4);
            cp16(smB + i * (STAGE_FLOATS * 4) + j * 16, Bsrc + (size_t)i * STAGE_FLOATS + j * 4);
        }
        cp_commit();
    }

    float acc[4][4][4];
    #pragma unroll
    for (int mf = 0; mf < 4; mf++)
        #pragma unroll
        for (int f = 0; f < 4; f++)
            #pragma unroll
            for (int q = 0; q < 4; q++) acc[mf][f][q] = 0.0f;

    int st = 0, fs = STAGES - 1;
    for (int i = 0; i < NITER; i++) {
        cp_wait1();
        __syncthreads();

        if (i + STAGES - 1 < NITER) {
            #pragma unroll
            for (int j = 0; j < 4; j++) {
                cp16(smA + fs * (STAGE_FLOATS * 4) + j * 16,
                     Asrc + (size_t)(i + STAGES - 1) * STAGE_FLOATS + j * 4);
                cp16(smB + fs * (STAGE_FLOATS * 4) + j * 16,
                     Bsrc + (size_t)(i + STAGES - 1) * STAGE_FLOATS + j * 4);
            }
        }
        cp_commit();

        const float* As = sm + st * STAGE_FLOATS;
        const float* Bs = sm + STAGES * STAGE_FLOATS + st * STAGE_FLOATS;

        #pragma unroll
        for (int ks = 0; ks < 4; ks++) {
            // A: 4 LDS.128 -> full a-fragments for 4 m-frags
            float4 av[4];
            #pragma unroll
            for (int mf = 0; mf < 4; mf++)
                av[mf] = *(const float4*)&As[(ks * 8 + warprow * 4 + mf) * 128 + lane * 4];
            // B: 2 LDS.128 -> b-fragments for 4 n-frags (2 n-pairs)
            float4 bv[2];
            #pragma unroll
            for (int p = 0; p < 2; p++)
                bv[p] = *(const float4*)&Bs[(ks * 8 + warpcol * 2 + p) * 128 + lane * 4];

            #pragma unroll
            for (int mf = 0; mf < 4; mf++) {
                const uint32_t a0 = __float_as_uint(av[mf].x), a1 = __float_as_uint(av[mf].y);
                const uint32_t a2 = __float_as_uint(av[mf].z), a3 = __float_as_uint(av[mf].w);
                #pragma unroll
                for (int p = 0; p < 2; p++) {
                    mma8(acc[mf][2*p][0], acc[mf][2*p][1], acc[mf][2*p][2], acc[mf][2*p][3],
                         a0, a1, a2, a3,
                         __float_as_uint(bv[p].x), __float_as_uint(bv[p].y));
                    mma8(acc[mf][2*p+1][0], acc[mf][2*p+1][1], acc[mf][2*p+1][2], acc[mf][2*p+1][3],
                         a0, a1, a2, a3,
                         __float_as_uint(bv[p].z), __float_as_uint(bv[p].w));
                }
            }
        }

        st = (st + 1 == STAGES) ? 0 : st + 1;
        fs = (fs + 1 == STAGES) ? 0 : fs + 1;
    }

    // ---- epilogue ----
    const int g = lane >> 2, t = lane & 3;
    const int m0 = mt * BM, n0 = nt * BN;
    #pragma unroll
    for (int mf = 0; mf < 4; mf++) {
        const int row0 = m0 + warprow * 64 + mf * 16 + g;
        #pragma unroll
        for (int f = 0; f < 4; f++) {
            // f = 2*p + o: n-pair p (16 n), within-pair o (8 n)
            const int ncol = n0 + warpcol * 32 + (f >> 1) * 16 + (f & 1) * 8 + 2 * t;
            float* p0 = y + (size_t)row0 * OUT_F + ncol;
            float* p1 = p0 + (size_t)8 * OUT_F;
            *(float2*)p0 = make_float2(acc[mf][f][0], acc[mf][f][1]);
            *(float2*)p1 = make_float2(acc[mf][f][2], acc[mf][f][3]);
        }
    }
}

extern "C" void kernel_launch(void* const* d_in, const int* in_sizes, int n_in,
                              void* d_out, int out_size)
{
    const float* x  = (const float*)d_in[0];
    const int*   wp = (const int*)d_in[1];
    const float* ws = (const float*)d_in[2];
    const int*   wz = (const int*)d_in[3];
    float*       y  = (float*)d_out;

    static bool attr_set = false;
    if (!attr_set) {
        cudaFuncSetAttribute(gemm_kernel,
                             cudaFuncAttributeMaxDynamicSharedMemorySize, SMEM_BYTES);
        attr_set = true;
    }

    prep_x_kernel<<<(TOKENS * (IN_F / 4)) / 256, 256>>>(x);
    prep_w_kernel<<<(OUT_F * (IN_F / 4)) / 256, 256>>>(wp, ws, wz);
    gemm_kernel<<<dim3(TOKENS / BM, OUT_F / BN), NTHREADS, SMEM_BYTES>>>(y);
}

// round 8
// speedup vs baseline: 3.0435x; 1.9607x over previous
#include <cuda_runtime.h>
#include <cuda_fp16.h>
#include <cstdint>

// ---------------- problem constants ----------------
#define TOKENS 4096
#define IN_F   4096
#define OUT_F  11008
#define NGRP   32

// ---------------- tile config ----------------
#define BM 128
#define BN 128
#define BK 64
#define NITER (IN_F / BK)        // 64
#define STAGES 3
#define STAGE_HALVES 8192        // 16KB per operand per stage (BM*BK halves)
#define TILE_HALVES (NITER * STAGE_HALVES)
#define NTHREADS 256

// ---------------- persistent scratch ----------------
__device__ __half g_xs[(size_t)TOKENS * IN_F];    // x fp16, A-fragment-tiled
__device__ __half g_wd[(size_t)OUT_F * IN_F];     // W dequant fp16, B-fragment-tiled

__device__ __forceinline__ uint32_t smem_u32(const void* p) {
    uint32_t a;
    asm("{ .reg .u64 t; cvta.to.shared.u64 t, %1; cvt.u32.u64 %0, t; }" : "=r"(a) : "l"(p));
    return a;
}
__device__ __forceinline__ void cp16(uint32_t dst, const void* src) {
    asm volatile("cp.async.cg.shared.global [%0], [%1], 16;" :: "r"(dst), "l"(src) : "memory");
}
__device__ __forceinline__ void cp_commit() { asm volatile("cp.async.commit_group;" ::: "memory"); }
__device__ __forceinline__ void cp_wait1()  { asm volatile("cp.async.wait_group 1;" ::: "memory"); }

__device__ __forceinline__ void mma16(float& d0, float& d1, float& d2, float& d3,
                                      uint32_t a0, uint32_t a1, uint32_t a2, uint32_t a3,
                                      uint32_t b0, uint32_t b1) {
    asm volatile("mma.sync.aligned.m16n8k16.row.col.f32.f16.f16.f32 "
                 "{%0,%1,%2,%3}, {%4,%5,%6,%7}, {%8,%9}, {%0,%1,%2,%3};"
                 : "+f"(d0), "+f"(d1), "+f"(d2), "+f"(d3)
                 : "r"(a0), "r"(a1), "r"(a2), "r"(a3), "r"(b0), "r"(b1));
}

// ============ prepass 1: x -> fp16, A-fragment-register-contiguous tiling ============
// Stage (mt,kst) = 32 blocks (blk = ks*8 + mb) of 256 halves (16m x 16k).
// Lane (of block): lane = (m&7)*4 + ((k&15)>>1); lane's 16B = 4 half2 regs:
//   r0=(m,k),(m,k+1)  r1=(m+8,k),(m+8,k+1)  r2=(m,k+8),(m,k+9)  r3=(m+8,k+8),(m+8,k+9)
__global__ void __launch_bounds__(256)
prep_x_kernel(const float* __restrict__ x)
{
    const int gid  = blockIdx.x * 256 + threadIdx.x;
    const int lane = gid & 31;
    const int blk  = (gid >> 5) & 31;
    const int stg  = gid >> 10;            // mt*64 + kst
    const int kst  = stg & 63;
    const int mt   = stg >> 6;
    const int ks = blk >> 3, mb = blk & 7;
    const int m = mt * 128 + mb * 16 + (lane >> 2);
    const int k = kst * 64 + ks * 16 + (lane & 3) * 2;

    const float* xr = x + (size_t)m * IN_F + k;
    const float2 v0 = *(const float2*)(xr);
    const float2 v1 = *(const float2*)(xr + (size_t)8 * IN_F);
    const float2 v2 = *(const float2*)(xr + 8);
    const float2 v3 = *(const float2*)(xr + (size_t)8 * IN_F + 8);

    __half2 h0 = __floats2half2_rn(v0.x, v0.y);
    __half2 h1 = __floats2half2_rn(v1.x, v1.y);
    __half2 h2 = __floats2half2_rn(v2.x, v2.y);
    __half2 h3 = __floats2half2_rn(v3.x, v3.y);

    uint4 o;
    o.x = *(uint32_t*)&h0; o.y = *(uint32_t*)&h1;
    o.z = *(uint32_t*)&h2; o.w = *(uint32_t*)&h3;
    *(uint4*)(g_xs + (size_t)stg * STAGE_HALVES + blk * 256 + lane * 8) = o;
}

// ============ prepass 2: W -> dequant fp16, B-fragment n-pair tiling ============
// Stage (nt,kst) = 32 blocks (blk = ks*8 + np; np = pair of 16 n) of 256 halves.
// Lane: lane = (n&7)*4 + ((k&15)>>1); lane's 16B:
//   r0=(k,n),(k+1,n)  r1=(k+8,n),(k+9,n)  r2=(k,n+8),(k+1,n+8)  r3=(k+8,n+8),(k+9,n+8)
__global__ void __launch_bounds__(256)
prep_w_kernel(const int*   __restrict__ wp,
              const float* __restrict__ ws,
              const int*   __restrict__ wz)
{
    const int gid  = blockIdx.x * 256 + threadIdx.x;
    const int lane = gid & 31;
    const int blk  = (gid >> 5) & 31;
    const int stg  = gid >> 10;            // nt*64 + kst
    const int kst  = stg & 63;
    const int nt   = stg >> 6;
    const int ks = blk >> 3, np = blk & 7;
    const int n = nt * 128 + np * 16 + (lane >> 2);
    const int k = kst * 64 + ks * 16 + (lane & 3) * 2;
    const int grp = k >> 7;                // whole 16-k block in one group

    const int* r0 = wp + (size_t)n * 2048;     // one packed byte per int32
    const int* r1 = r0 + (size_t)8 * 2048;
    const int i0 = k >> 1;                     // k even: (k,k+1) in one byte
    const int b00 = r0[i0], b01 = r0[i0 + 4];  // (k,k+1), (k+8,k+9) for row n
    const int b10 = r1[i0], b11 = r1[i0 + 4];  // same for row n+8

    const float s0 = ws[(size_t)n * NGRP + grp];
    const float c0 = (-8.0f - (float)wz[(size_t)n * NGRP + grp]) * s0;
    const float s1 = ws[(size_t)(n + 8) * NGRP + grp];
    const float c1 = (-8.0f - (float)wz[(size_t)(n + 8) * NGRP + grp]) * s1;

    #define DQ(b, sh, s, c) fmaf((float)(int)((((uint32_t)(b) >> (sh)) & 15u) ^ 8u), (s), (c))
    __half2 h0 = __floats2half2_rn(DQ(b00, 0, s0, c0), DQ(b00, 4, s0, c0));
    __half2 h1 = __floats2half2_rn(DQ(b01, 0, s0, c0), DQ(b01, 4, s0, c0));
    __half2 h2 = __floats2half2_rn(DQ(b10, 0, s1, c1), DQ(b10, 4, s1, c1));
    __half2 h3 = __floats2half2_rn(DQ(b11, 0, s1, c1), DQ(b11, 4, s1, c1));
    #undef DQ

    uint4 o;
    o.x = *(uint32_t*)&h0; o.y = *(uint32_t*)&h1;
    o.z = *(uint32_t*)&h2; o.w = *(uint32_t*)&h3;
    *(uint4*)(g_wd + (size_t)stg * STAGE_HALVES + blk * 256 + lane * 8) = o;
}

// ============ main GEMM: fp16 m16n8k16, 64x32 warp tiles, LDS.128 fragments ============
#define SMEM_BYTES (2 * STAGES * STAGE_HALVES * 2)   // 98304... = 96KB

__global__ void __launch_bounds__(NTHREADS, 2)
gemm_kernel(float* __restrict__ y)
{
    extern __shared__ __half sm[];   // [STAGES][8192] A then [STAGES][8192] B

    const int tid  = threadIdx.x;
    const int lane = tid & 31;
    const int wid  = tid >> 5;
    const int warprow = wid >> 2;       // 0..1  (64 m)
    const int warpcol = wid & 3;        // 0..3  (32 n)
    const int mt = blockIdx.x;          // m fastest: co-resident CTAs share nt
    const int nt = blockIdx.y;

    const __half* Asrc = g_xs + (size_t)mt * TILE_HALVES + tid * 32;
    const __half* Bsrc = g_wd + (size_t)nt * TILE_HALVES + tid * 32;
    const uint32_t smA = smem_u32(sm) + tid * 64;
    const uint32_t smB = smA + STAGES * STAGE_HALVES * 2;

    #pragma unroll
    for (int i = 0; i < STAGES - 1; i++) {
        #pragma unroll
        for (int j = 0; j < 4; j++) {
            cp16(smA + i * (STAGE_HALVES * 2) + j * 16, Asrc + (size_t)i * STAGE_HALVES + j * 8);
            cp16(smB + i * (STAGE_HALVES * 2) + j * 16, Bsrc + (size_t)i * STAGE_HALVES + j * 8);
        }
        cp_commit();
    }

    float acc[4][4][4];
    #pragma unroll
    for (int mf = 0; mf < 4; mf++)
        #pragma unroll
        for (int f = 0; f < 4; f++)
            #pragma unroll
            for (int q = 0; q < 4; q++) acc[mf][f][q] = 0.0f;

    int st = 0, fs = STAGES - 1;
    for (int i = 0; i < NITER; i++) {
        cp_wait1();
        __syncthreads();

        if (i + STAGES - 1 < NITER) {
            #pragma unroll
            for (int j = 0; j < 4; j++) {
                cp16(smA + fs * (STAGE_HALVES * 2) + j * 16,
                     Asrc + (size_t)(i + STAGES - 1) * STAGE_HALVES + j * 8);
                cp16(smB + fs * (STAGE_HALVES * 2) + j * 16,
                     Bsrc + (size_t)(i + STAGES - 1) * STAGE_HALVES + j * 8);
            }
        }
        cp_commit();

        const __half* As = sm + st * STAGE_HALVES;
        const __half* Bs = sm + STAGES * STAGE_HALVES + st * STAGE_HALVES;

        #pragma unroll
        for (int ks = 0; ks < 4; ks++) {
            // A: 4 LDS.128 -> full m16n8k16 a-fragments for 4 m-frags
            uint4 av[4];
            #pragma unroll
            for (int mf = 0; mf < 4; mf++)
                av[mf] = *(const uint4*)&As[(ks * 8 + warprow * 4 + mf) * 256 + lane * 8];
            // B: 2 LDS.128 -> b-fragments for 4 n-frags (2 n-pairs)
            uint4 bv[2];
            #pragma unroll
            for (int p = 0; p < 2; p++)
                bv[p] = *(const uint4*)&Bs[(ks * 8 + warpcol * 2 + p) * 256 + lane * 8];

            #pragma unroll
            for (int mf = 0; mf < 4; mf++) {
                #pragma unroll
                for (int p = 0; p < 2; p++) {
                    mma16(acc[mf][2*p][0], acc[mf][2*p][1], acc[mf][2*p][2], acc[mf][2*p][3],
                          av[mf].x, av[mf].y, av[mf].z, av[mf].w,
                          bv[p].x, bv[p].y);
                    mma16(acc[mf][2*p+1][0], acc[mf][2*p+1][1], acc[mf][2*p+1][2], acc[mf][2*p+1][3],
                          av[mf].x, av[mf].y, av[mf].z, av[mf].w,
                          bv[p].z, bv[p].w);
                }
            }
        }

        st = (st + 1 == STAGES) ? 0 : st + 1;
        fs = (fs + 1 == STAGES) ? 0 : fs + 1;
    }

    // ---- epilogue ----
    const int g = lane >> 2, t = lane & 3;
    const int m0 = mt * BM, n0 = nt * BN;
    #pragma unroll
    for (int mf = 0; mf < 4; mf++) {
        const int row0 = m0 + warprow * 64 + mf * 16 + g;
        #pragma unroll
        for (int f = 0; f < 4; f++) {
            // f = 2*p + o: n-pair p (16 n), within-pair o (8 n)
            const int ncol = n0 + warpcol * 32 + (f >> 1) * 16 + (f & 1) * 8 + 2 * t;
            float* p0 = y + (size_t)row0 * OUT_F + ncol;
            float* p1 = p0 + (size_t)8 * OUT_F;
            *(float2*)p0 = make_float2(acc[mf][f][0], acc[mf][f][1]);
            *(float2*)p1 = make_float2(acc[mf][f][2], acc[mf][f][3]);
        }
    }
}

extern "C" void kernel_launch(void* const* d_in, const int* in_sizes, int n_in,
                              void* d_out, int out_size)
{
    const float* x  = (const float*)d_in[0];
    const int*   wp = (const int*)d_in[1];
    const float* ws = (const float*)d_in[2];
    const int*   wz = (const int*)d_in[3];
    float*       y  = (float*)d_out;

    static bool attr_set = false;
    if (!attr_set) {
        cudaFuncSetAttribute(gemm_kernel,
                             cudaFuncAttributeMaxDynamicSharedMemorySize, SMEM_BYTES);
        attr_set = true;
    }

    prep_x_kernel<<<(TOKENS * (IN_F / 8)) / 256, 256>>>(x);
    prep_w_kernel<<<(OUT_F * (IN_F / 8)) / 256, 256>>>(wp, ws, wz);
    gemm_kernel<<<dim3(TOKENS / BM, OUT_F / BN), NTHREADS, SMEM_BYTES>>>(y);
}

// round 11
// speedup vs baseline: 3.6837x; 1.2104x over previous
#include <cuda_runtime.h>
#include <cuda_fp16.h>
#include <cstdint>

// ---------------- problem constants ----------------
#define TOKENS 4096
#define IN_F   4096
#define OUT_F  11008
#define NGRP   32

// ---------------- tile config ----------------
#define BM 128
#define BN 128
#define BK 64
#define NITER (IN_F / BK)        // 64
#define NSTEP (IN_F / 16)        // 256 k-steps of 16
#define STEP_HALVES 2048         // halves per (128-row, 16-k) fragment slab
#define TILE_HALVES ((size_t)NSTEP * STEP_HALVES)
#define STAGES 3
#define STAGE_HALVES 8192        // B stage: BN*BK halves = 16KB
#define NTHREADS 256

// ---------------- persistent scratch ----------------
__device__ __half g_xs[(size_t)TOKENS * IN_F];    // x fp16, A-fragment-tiled
__device__ __half g_wd[(size_t)OUT_F * IN_F];     // W dequant fp16, B-fragment-tiled

__device__ __forceinline__ uint32_t smem_u32(const void* p) {
    uint32_t a;
    asm("{ .reg .u64 t; cvta.to.shared.u64 t, %1; cvt.u32.u64 %0, t; }" : "=r"(a) : "l"(p));
    return a;
}
__device__ __forceinline__ void cp16(uint32_t dst, const void* src) {
    asm volatile("cp.async.cg.shared.global [%0], [%1], 16;" :: "r"(dst), "l"(src) : "memory");
}
__device__ __forceinline__ void cp_commit() { asm volatile("cp.async.commit_group;" ::: "memory"); }
__device__ __forceinline__ void cp_wait1()  { asm volatile("cp.async.wait_group 1;" ::: "memory"); }

__device__ __forceinline__ void mma16(float& d0, float& d1, float& d2, float& d3,
                                      uint32_t a0, uint32_t a1, uint32_t a2, uint32_t a3,
                                      uint32_t b0, uint32_t b1) {
    asm volatile("mma.sync.aligned.m16n8k16.row.col.f32.f16.f16.f32 "
                 "{%0,%1,%2,%3}, {%4,%5,%6,%7}, {%8,%9}, {%0,%1,%2,%3};"
                 : "+f"(d0), "+f"(d1), "+f"(d2), "+f"(d3)
                 : "r"(a0), "r"(a1), "r"(a2), "r"(a3), "r"(b0), "r"(b1));
}

// ============ prepass 1: x -> fp16, A-fragment-register-contiguous tiling ============
// (identical output bytes to the R8-passing version)
__global__ void __launch_bounds__(256)
prep_x_kernel(const float* __restrict__ x)
{
    const int gid  = blockIdx.x * 256 + threadIdx.x;
    const int lane = gid & 31;
    const int blk  = (gid >> 5) & 31;          // ks*8 + mb within 64-k chunk
    const int stg  = gid >> 10;                // mt*64 + chunk
    const int chunk = stg & 63;
    const int mt   = stg >> 6;
    const int ks = blk >> 3, mb = blk & 7;
    const int m = mt * 128 + mb * 16 + (lane >> 2);
    const int k = chunk * 64 + ks * 16 + (lane & 3) * 2;

    const float* xr = x + (size_t)m * IN_F + k;
    const float2 v0 = *(const float2*)(xr);
    const float2 v1 = *(const float2*)(xr + (size_t)8 * IN_F);
    const float2 v2 = *(const float2*)(xr + 8);
    const float2 v3 = *(const float2*)(xr + (size_t)8 * IN_F + 8);

    __half2 h0 = __floats2half2_rn(v0.x, v0.y);
    __half2 h1 = __floats2half2_rn(v1.x, v1.y);
    __half2 h2 = __floats2half2_rn(v2.x, v2.y);
    __half2 h3 = __floats2half2_rn(v3.x, v3.y);

    uint4 o;
    o.x = *(uint32_t*)&h0; o.y = *(uint32_t*)&h1;
    o.z = *(uint32_t*)&h2; o.w = *(uint32_t*)&h3;
    *(uint4*)(g_xs + (size_t)mt * TILE_HALVES
              + (size_t)(chunk * 4 + ks) * STEP_HALVES + mb * 256 + lane * 8) = o;
}

// ============ prepass 2: W -> dequant fp16, B-fragment n-pair tiling ============
__global__ void __launch_bounds__(256)
prep_w_kernel(const int*   __restrict__ wp,
              const float* __restrict__ ws,
              const int*   __restrict__ wz)
{
    const int gid  = blockIdx.x * 256 + threadIdx.x;
    const int lane = gid & 31;
    const int blk  = (gid >> 5) & 31;
    const int stg  = gid >> 10;                // nt*64 + chunk
    const int chunk = stg & 63;
    const int nt   = stg >> 6;
    const int ks = blk >> 3, np = blk & 7;
    const int n = nt * 128 + np * 16 + (lane >> 2);
    const int k = chunk * 64 + ks * 16 + (lane & 3) * 2;
    const int grp = k >> 7;

    const int* r0 = wp + (size_t)n * 2048;     // one packed byte per int32
    const int* r1 = r0 + (size_t)8 * 2048;
    const int i0 = k >> 1;
    const int b00 = r0[i0], b01 = r0[i0 + 4];
    const int b10 = r1[i0], b11 = r1[i0 + 4];

    const float s0 = ws[(size_t)n * NGRP + grp];
    const float c0 = (-8.0f - (float)wz[(size_t)n * NGRP + grp]) * s0;
    const float s1 = ws[(size_t)(n + 8) * NGRP + grp];
    const float c1 = (-8.0f - (float)wz[(size_t)(n + 8) * NGRP + grp]) * s1;

    #define DQ(b, sh, s, c) fmaf((float)(int)((((uint32_t)(b) >> (sh)) & 15u) ^ 8u), (s), (c))
    __half2 h0 = __floats2half2_rn(DQ(b00, 0, s0, c0), DQ(b00, 4, s0, c0));
    __half2 h1 = __floats2half2_rn(DQ(b01, 0, s0, c0), DQ(b01, 4, s0, c0));
    __half2 h2 = __floats2half2_rn(DQ(b10, 0, s1, c1), DQ(b10, 4, s1, c1));
    __half2 h3 = __floats2half2_rn(DQ(b11, 0, s1, c1), DQ(b11, 4, s1, c1));
    #undef DQ

    uint4 o;
    o.x = *(uint32_t*)&h0; o.y = *(uint32_t*)&h1;
    o.z = *(uint32_t*)&h2; o.w = *(uint32_t*)&h3;
    *(uint4*)(g_wd + (size_t)nt * TILE_HALVES
              + (size_t)(chunk * 4 + ks) * STEP_HALVES + np * 256 + lane * 8) = o;
}

// ============ main GEMM: B via cp.async smem (R8-proven), A via direct LDG ============
#define SMEM_BYTES (STAGES * STAGE_HALVES * 2)   // 48KB (B only)

__global__ void __launch_bounds__(NTHREADS, 2)
gemm_kernel(float* __restrict__ y)
{
    extern __shared__ __half sm[];   // [STAGES][8192] B stages

    const int tid  = threadIdx.x;
    const int lane = tid & 31;
    const int wid  = tid >> 5;
    const int warprow = wid >> 2;       // 0..1  (64 m)
    const int warpcol = wid & 3;        // 0..3  (32 n)
    const int mt = blockIdx.x;          // m fastest: co-resident CTAs share nt
    const int nt = blockIdx.y;

    // ---- B pipeline (exactly as R8) ----
    const __half* Bsrc = g_wd + (size_t)nt * TILE_HALVES + tid * 32;
    const uint32_t smB = smem_u32(sm) + tid * 64;

    #pragma unroll
    for (int i = 0; i < STAGES - 1; i++) {
        #pragma unroll
        for (int j = 0; j < 4; j++)
            cp16(smB + i * (STAGE_HALVES * 2) + j * 16, Bsrc + (size_t)i * STAGE_HALVES + j * 8);
        cp_commit();
    }

    // ---- A: warp-private direct fragment stream ----
    const __half* Abase = g_xs + (size_t)mt * TILE_HALVES
                        + (size_t)(warprow * 4) * 256 + (size_t)lane * 8;

    float acc[4][4][4];
    #pragma unroll
    for (int mf = 0; mf < 4; mf++)
        #pragma unroll
        for (int f = 0; f < 4; f++)
            #pragma unroll
            for (int q = 0; q < 4; q++) acc[mf][f][q] = 0.0f;

    // ping-pong A buffers: even k-steps in aEv, odd in aOd (parity compile-time per ks)
    uint4 aEv[4], aOd[4];
    #pragma unroll
    for (int mf = 0; mf < 4; mf++)
        aEv[mf] = *(const uint4*)(Abase + mf * 256);   // s = 0

    int st = 0, fs = STAGES - 1;
    for (int i = 0; i < NITER; i++) {
        cp_wait1();
        __syncthreads();

        if (i + STAGES - 1 < NITER) {
            #pragma unroll
            for (int j = 0; j < 4; j++)
                cp16(smB + fs * (STAGE_HALVES * 2) + j * 16,
                     Bsrc + (size_t)(i + STAGES - 1) * STAGE_HALVES + j * 8);
        }
        cp_commit();

        const __half* Bs = sm + st * STAGE_HALVES;

        #pragma unroll
        for (int ks = 0; ks < 4; ks++) {
            // prefetch A fragments for k-step s+1 into the opposite-parity buffer
            const int snx = i * 4 + ks + 1;
            if (snx < NSTEP) {
                const __half* An = Abase + (size_t)snx * STEP_HALVES;
                if ((ks & 1) == 0) {
                    #pragma unroll
                    for (int mf = 0; mf < 4; mf++)
                        aOd[mf] = *(const uint4*)(An + mf * 256);
                } else {
                    #pragma unroll
                    for (int mf = 0; mf < 4; mf++)
                        aEv[mf] = *(const uint4*)(An + mf * 256);
                }
            }

            // B: 2 LDS.128 -> b-fragments for 4 n-frags (2 n-pairs)
            uint4 bv[2];
            #pragma unroll
            for (int p = 0; p < 2; p++)
                bv[p] = *(const uint4*)&Bs[(ks * 8 + warpcol * 2 + p) * 256 + lane * 8];

            const uint4* ac = ((ks & 1) == 0) ? aEv : aOd;
            #pragma unroll
            for (int mf = 0; mf < 4; mf++) {
                #pragma unroll
                for (int p = 0; p < 2; p++) {
                    mma16(acc[mf][2*p][0], acc[mf][2*p][1], acc[mf][2*p][2], acc[mf][2*p][3],
                          ac[mf].x, ac[mf].y, ac[mf].z, ac[mf].w,
                          bv[p].x, bv[p].y);
                    mma16(acc[mf][2*p+1][0], acc[mf][2*p+1][1], acc[mf][2*p+1][2], acc[mf][2*p+1][3],
                          ac[mf].x, ac[mf].y, ac[mf].z, ac[mf].w,
                          bv[p].z, bv[p].w);
                }
            }
        }

        st = (st + 1 == STAGES) ? 0 : st + 1;
        fs = (fs + 1 == STAGES) ? 0 : fs + 1;
    }

    // ---- epilogue (verbatim R8) ----
    const int g = lane >> 2, t = lane & 3;
    const int m0 = mt * BM, n0 = nt * BN;
    #pragma unroll
    for (int mf = 0; mf < 4; mf++) {
        const int row0 = m0 + warprow * 64 + mf * 16 + g;
        #pragma unroll
        for (int f = 0; f < 4; f++) {
            const int ncol = n0 + warpcol * 32 + (f >> 1) * 16 + (f & 1) * 8 + 2 * t;
            float* p0 = y + (size_t)row0 * OUT_F + ncol;
            float* p1 = p0 + (size_t)8 * OUT_F;
            *(float2*)p0 = make_float2(acc[mf][f][0], acc[mf][f][1]);
            *(float2*)p1 = make_float2(acc[mf][f][2], acc[mf][f][3]);
        }
    }
}

extern "C" void kernel_launch(void* const* d_in, const int* in_sizes, int n_in,
                              void* d_out, int out_size)
{
    const float* x  = (const float*)d_in[0];
    const int*   wp = (const int*)d_in[1];
    const float* ws = (const float*)d_in[2];
    const int*   wz = (const int*)d_in[3];
    float*       y  = (float*)d_out;

    cudaFuncSetAttribute(gemm_kernel,
                         cudaFuncAttributeMaxDynamicSharedMemorySize, SMEM_BYTES);

    prep_x_kernel<<<(TOKENS * (IN_F / 8)) / 256, 256>>>(x);
    prep_w_kernel<<<(OUT_F * (IN_F / 8)) / 256, 256>>>(wp, ws, wz);
    gemm_kernel<<<dim3(TOKENS / BM, OUT_F / BN), NTHREADS, SMEM_BYTES>>>(y);
}

// round 13
// speedup vs baseline: 4.1588x; 1.1290x over previous
#include <cuda_runtime.h>
#include <cuda_fp16.h>
#include <cstdint>

// ---------------- problem constants ----------------
#define TOKENS 4096
#define IN_F   4096
#define OUT_F  11008
#define NGRP   32

// ---------------- tile config ----------------
#define BM 128
#define BN 128
#define NSTEP (IN_F / 16)        // 256 k-steps of 16
#define STEP_HALVES 2048         // halves per (128-row, 16-k) fragment slab
#define TILE_HALVES ((size_t)NSTEP * STEP_HALVES)
#define NTHREADS 128             // 4 warps: 2x2 grid of 64x64 warp tiles

// ---------------- persistent scratch ----------------
__device__ __half g_xs[(size_t)TOKENS * IN_F];    // x fp16, A-fragment-tiled
__device__ __half g_wd[(size_t)OUT_F * IN_F];     // W dequant fp16, B-fragment-tiled

__device__ __forceinline__ void mma16(float& d0, float& d1, float& d2, float& d3,
                                      uint32_t a0, uint32_t a1, uint32_t a2, uint32_t a3,
                                      uint32_t b0, uint32_t b1) {
    asm volatile("mma.sync.aligned.m16n8k16.row.col.f32.f16.f16.f32 "
                 "{%0,%1,%2,%3}, {%4,%5,%6,%7}, {%8,%9}, {%0,%1,%2,%3};"
                 : "+f"(d0), "+f"(d1), "+f"(d2), "+f"(d3)
                 : "r"(a0), "r"(a1), "r"(a2), "r"(a3), "r"(b0), "r"(b1));
}

// ============ prepass 1: x -> fp16, A-fragment-register-contiguous tiling ============
// (byte-identical to R8/R11-passing version)
__global__ void __launch_bounds__(256)
prep_x_kernel(const float* __restrict__ x)
{
    const int gid  = blockIdx.x * 256 + threadIdx.x;
    const int lane = gid & 31;
    const int blk  = (gid >> 5) & 31;          // ks*8 + mb within 64-k chunk
    const int stg  = gid >> 10;                // mt*64 + chunk
    const int chunk = stg & 63;
    const int mt   = stg >> 6;
    const int ks = blk >> 3, mb = blk & 7;
    const int m = mt * 128 + mb * 16 + (lane >> 2);
    const int k = chunk * 64 + ks * 16 + (lane & 3) * 2;

    const float* xr = x + (size_t)m * IN_F + k;
    const float2 v0 = *(const float2*)(xr);
    const float2 v1 = *(const float2*)(xr + (size_t)8 * IN_F);
    const float2 v2 = *(const float2*)(xr + 8);
    const float2 v3 = *(const float2*)(xr + (size_t)8 * IN_F + 8);

    __half2 h0 = __floats2half2_rn(v0.x, v0.y);
    __half2 h1 = __floats2half2_rn(v1.x, v1.y);
    __half2 h2 = __floats2half2_rn(v2.x, v2.y);
    __half2 h3 = __floats2half2_rn(v3.x, v3.y);

    uint4 o;
    o.x = *(uint32_t*)&h0; o.y = *(uint32_t*)&h1;
    o.z = *(uint32_t*)&h2; o.w = *(uint32_t*)&h3;
    *(uint4*)(g_xs + (size_t)mt * TILE_HALVES
              + (size_t)(chunk * 4 + ks) * STEP_HALVES + mb * 256 + lane * 8) = o;
}

// ============ prepass 2: W -> dequant fp16, B-fragment n-pair tiling ============
__global__ void __launch_bounds__(256)
prep_w_kernel(const int*   __restrict__ wp,
              const float* __restrict__ ws,
              const int*   __restrict__ wz)
{
    const int gid  = blockIdx.x * 256 + threadIdx.x;
    const int lane = gid & 31;
    const int blk  = (gid >> 5) & 31;
    const int stg  = gid >> 10;                // nt*64 + chunk
    const int chunk = stg & 63;
    const int nt   = stg >> 6;
    const int ks = blk >> 3, np = blk & 7;
    const int n = nt * 128 + np * 16 + (lane >> 2);
    const int k = chunk * 64 + ks * 16 + (lane & 3) * 2;
    const int grp = k >> 7;

    const int* r0 = wp + (size_t)n * 2048;     // one packed byte per int32
    const int* r1 = r0 + (size_t)8 * 2048;
    const int i0 = k >> 1;
    const int b00 = r0[i0], b01 = r0[i0 + 4];
    const int b10 = r1[i0], b11 = r1[i0 + 4];

    const float s0 = ws[(size_t)n * NGRP + grp];
    const float c0 = (-8.0f - (float)wz[(size_t)n * NGRP + grp]) * s0;
    const float s1 = ws[(size_t)(n + 8) * NGRP + grp];
    const float c1 = (-8.0f - (float)wz[(size_t)(n + 8) * NGRP + grp]) * s1;

    #define DQ(b, sh, s, c) fmaf((float)(int)((((uint32_t)(b) >> (sh)) & 15u) ^ 8u), (s), (c))
    __half2 h0 = __floats2half2_rn(DQ(b00, 0, s0, c0), DQ(b00, 4, s0, c0));
    __half2 h1 = __floats2half2_rn(DQ(b01, 0, s0, c0), DQ(b01, 4, s0, c0));
    __half2 h2 = __floats2half2_rn(DQ(b10, 0, s1, c1), DQ(b10, 4, s1, c1));
    __half2 h3 = __floats2half2_rn(DQ(b11, 0, s1, c1), DQ(b11, 4, s1, c1));
    #undef DQ

    uint4 o;
    o.x = *(uint32_t*)&h0; o.y = *(uint32_t*)&h1;
    o.z = *(uint32_t*)&h2; o.w = *(uint32_t*)&h3;
    *(uint4*)(g_wd + (size_t)nt * TILE_HALVES
              + (size_t)(chunk * 4 + ks) * STEP_HALVES + np * 256 + lane * 8) = o;
}

// ============ main GEMM: fully smem-free, 64x64 warp tiles, direct-LDG streams ============
__global__ void __launch_bounds__(NTHREADS, 2)
gemm_kernel(float* __restrict__ y)
{
    const int tid  = threadIdx.x;
    const int lane = tid & 31;
    const int wid  = tid >> 5;
    const int warprow = wid >> 1;       // 0..1  (64 m)
    const int warpcol = wid & 1;        // 0..1  (64 n)
    const int mt = blockIdx.x;          // m fastest: co-resident CTAs share nt
    const int nt = blockIdx.y;

    // warp-private fragment streams (half-pointer arithmetic ONLY)
    const __half* Abase = g_xs + (size_t)mt * TILE_HALVES
                        + (size_t)(warprow * 4) * 256 + (size_t)lane * 8;
    const __half* Bbase = g_wd + (size_t)nt * TILE_HALVES
                        + (size_t)(warpcol * 4) * 256 + (size_t)lane * 8;

    float acc[4][8][4];
    #pragma unroll
    for (int mf = 0; mf < 4; mf++)
        #pragma unroll
        for (int f = 0; f < 8; f++)
            #pragma unroll
            for (int q = 0; q < 4; q++) acc[mf][f][q] = 0.0f;

    // parity ping-pong fragment buffers (proven R11 mechanism)
    uint4 aEv[4], aOd[4], bEv[4], bOd[4];
    #pragma unroll
    for (int mf = 0; mf < 4; mf++) aEv[mf] = *(const uint4*)(Abase + mf * 256);
    #pragma unroll
    for (int p = 0; p < 4; p++)    bEv[p]  = *(const uint4*)(Bbase + p * 256);

    for (int s = 0; s < NSTEP; s += 2) {
        // ---- even step: compute from Ev, prefetch s+1 into Od ----
        {
            const __half* An = Abase + (size_t)(s + 1) * STEP_HALVES;
            const __half* Bn = Bbase + (size_t)(s + 1) * STEP_HALVES;
            #pragma unroll
            for (int mf = 0; mf < 4; mf++) aOd[mf] = *(const uint4*)(An + mf * 256);
            #pragma unroll
            for (int p = 0; p < 4; p++)    bOd[p]  = *(const uint4*)(Bn + p * 256);
        }
        #pragma unroll
        for (int mf = 0; mf < 4; mf++)
            #pragma unroll
            for (int p = 0; p < 4; p++) {
                mma16(acc[mf][2*p][0], acc[mf][2*p][1], acc[mf][2*p][2], acc[mf][2*p][3],
                      aEv[mf].x, aEv[mf].y, aEv[mf].z, aEv[mf].w,
                      bEv[p].x, bEv[p].y);
                mma16(acc[mf][2*p+1][0], acc[mf][2*p+1][1], acc[mf][2*p+1][2], acc[mf][2*p+1][3],
                      aEv[mf].x, aEv[mf].y, aEv[mf].z, aEv[mf].w,
                      bEv[p].z, bEv[p].w);
            }

        // ---- odd step: compute from Od, prefetch s+2 into Ev ----
        if (s + 2 < NSTEP) {
            const __half* An = Abase + (size_t)(s + 2) * STEP_HALVES;
            const __half* Bn = Bbase + (size_t)(s + 2) * STEP_HALVES;
            #pragma unroll
            for (int mf = 0; mf < 4; mf++) aEv[mf] = *(const uint4*)(An + mf * 256);
            #pragma unroll
            for (int p = 0; p < 4; p++)    bEv[p]  = *(const uint4*)(Bn + p * 256);
        }
        #pragma unroll
        for (int mf = 0; mf < 4; mf++)
            #pragma unroll
            for (int p = 0; p < 4; p++) {
                mma16(acc[mf][2*p][0], acc[mf][2*p][1], acc[mf][2*p][2], acc[mf][2*p][3],
                      aOd[mf].x, aOd[mf].y, aOd[mf].z, aOd[mf].w,
                      bOd[p].x, bOd[p].y);
                mma16(acc[mf][2*p+1][0], acc[mf][2*p+1][1], acc[mf][2*p+1][2], acc[mf][2*p+1][3],
                      aOd[mf].x, aOd[mf].y, aOd[mf].z, aOd[mf].w,
                      bOd[p].z, bOd[p].w);
            }
    }

    // ---- epilogue ----
    const int g = lane >> 2, t = lane & 3;
    const int m0 = mt * BM, n0 = nt * BN;
    #pragma unroll
    for (int mf = 0; mf < 4; mf++) {
        const int row0 = m0 + warprow * 64 + mf * 16 + g;
        #pragma unroll
        for (int f = 0; f < 8; f++) {
            // f = 2*p + o: n-pair p (16 n), within-pair o (8 n)
            const int ncol = n0 + warpcol * 64 + (f >> 1) * 16 + (f & 1) * 8 + 2 * t;
            float* p0 = y + (size_t)row0 * OUT_F + ncol;
            float* p1 = p0 + (size_t)8 * OUT_F;
            *(float2*)p0 = make_float2(acc[mf][f][0], acc[mf][f][1]);
            *(float2*)p1 = make_float2(acc[mf][f][2], acc[mf][f][3]);
        }
    }
}

extern "C" void kernel_launch(void* const* d_in, const int* in_sizes, int n_in,
                              void* d_out, int out_size)
{
    const float* x  = (const float*)d_in[0];
    const int*   wp = (const int*)d_in[1];
    const float* ws = (const float*)d_in[2];
    const int*   wz = (const int*)d_in[3];
    float*       y  = (float*)d_out;

    prep_x_kernel<<<(TOKENS * (IN_F / 8)) / 256, 256>>>(x);
    prep_w_kernel<<<(OUT_F * (IN_F / 8)) / 256, 256>>>(wp, ws, wz);
    gemm_kernel<<<dim3(TOKENS / BM, OUT_F / BN), NTHREADS>>>(y);
}

// round 14
// speedup vs baseline: 4.1788x; 1.0048x over previous
#include <cuda_runtime.h>
#include <cuda_fp16.h>
#include <cstdint>

// ---------------- problem constants ----------------
#define TOKENS 4096
#define IN_F   4096
#define OUT_F  11008
#define NGRP   32

// ---------------- tile config ----------------
#define BM 128
#define BN 128
#define NSTEP (IN_F / 16)        // 256 k-steps of 16
#define STEP_HALVES 2048         // halves per (128-row, 16-k) fragment slab
#define TILE_HALVES ((size_t)NSTEP * STEP_HALVES)
#define NTHREADS 128             // 4 warps: 2x2 grid of 64x64 warp tiles

// ---------------- persistent scratch ----------------
__device__ __half g_xs[(size_t)TOKENS * IN_F];    // x fp16, A-fragment-tiled
__device__ __half g_wd[(size_t)OUT_F * IN_F];     // W dequant fp16, B-fragment-tiled

__device__ __forceinline__ void mma16(float& d0, float& d1, float& d2, float& d3,
                                      uint32_t a0, uint32_t a1, uint32_t a2, uint32_t a3,
                                      uint32_t b0, uint32_t b1) {
    asm volatile("mma.sync.aligned.m16n8k16.row.col.f32.f16.f16.f32 "
                 "{%0,%1,%2,%3}, {%4,%5,%6,%7}, {%8,%9}, {%0,%1,%2,%3};"
                 : "+f"(d0), "+f"(d1), "+f"(d2), "+f"(d3)
                 : "r"(a0), "r"(a1), "r"(a2), "r"(a3), "r"(b0), "r"(b1));
}

__device__ __forceinline__ void stg_cs_v2(float* p, float a, float b) {
    asm volatile("st.global.cs.v2.f32 [%0], {%1, %2};" :: "l"(p), "f"(a), "f"(b) : "memory");
}

// ============ prepass 1: x -> fp16, A-fragment-register-contiguous tiling ============
// (byte-identical to R8/R11/R13-passing version)
__global__ void __launch_bounds__(256)
prep_x_kernel(const float* __restrict__ x)
{
    const int gid  = blockIdx.x * 256 + threadIdx.x;
    const int lane = gid & 31;
    const int blk  = (gid >> 5) & 31;          // ks*8 + mb within 64-k chunk
    const int stg  = gid >> 10;                // mt*64 + chunk
    const int chunk = stg & 63;
    const int mt   = stg >> 6;
    const int ks = blk >> 3, mb = blk & 7;
    const int m = mt * 128 + mb * 16 + (lane >> 2);
    const int k = chunk * 64 + ks * 16 + (lane & 3) * 2;

    const float* xr = x + (size_t)m * IN_F + k;
    const float2 v0 = *(const float2*)(xr);
    const float2 v1 = *(const float2*)(xr + (size_t)8 * IN_F);
    const float2 v2 = *(const float2*)(xr + 8);
    const float2 v3 = *(const float2*)(xr + (size_t)8 * IN_F + 8);

    __half2 h0 = __floats2half2_rn(v0.x, v0.y);
    __half2 h1 = __floats2half2_rn(v1.x, v1.y);
    __half2 h2 = __floats2half2_rn(v2.x, v2.y);
    __half2 h3 = __floats2half2_rn(v3.x, v3.y);

    uint4 o;
    o.x = *(uint32_t*)&h0; o.y = *(uint32_t*)&h1;
    o.z = *(uint32_t*)&h2; o.w = *(uint32_t*)&h3;
    *(uint4*)(g_xs + (size_t)mt * TILE_HALVES
              + (size_t)(chunk * 4 + ks) * STEP_HALVES + mb * 256 + lane * 8) = o;
}

// ============ prepass 2: W -> dequant fp16, B-fragment n-pair tiling ============
__global__ void __launch_bounds__(256)
prep_w_kernel(const int*   __restrict__ wp,
              const float* __restrict__ ws,
              const int*   __restrict__ wz)
{
    const int gid  = blockIdx.x * 256 + threadIdx.x;
    const int lane = gid & 31;
    const int blk  = (gid >> 5) & 31;
    const int stg  = gid >> 10;                // nt*64 + chunk
    const int chunk = stg & 63;
    const int nt   = stg >> 6;
    const int ks = blk >> 3, np = blk & 7;
    const int n = nt * 128 + np * 16 + (lane >> 2);
    const int k = chunk * 64 + ks * 16 + (lane & 3) * 2;
    const int grp = k >> 7;

    const int* r0 = wp + (size_t)n * 2048;     // one packed byte per int32
    const int* r1 = r0 + (size_t)8 * 2048;
    const int i0 = k >> 1;
    const int b00 = r0[i0], b01 = r0[i0 + 4];
    const int b10 = r1[i0], b11 = r1[i0 + 4];

    const float s0 = ws[(size_t)n * NGRP + grp];
    const float c0 = (-8.0f - (float)wz[(size_t)n * NGRP + grp]) * s0;
    const float s1 = ws[(size_t)(n + 8) * NGRP + grp];
    const float c1 = (-8.0f - (float)wz[(size_t)(n + 8) * NGRP + grp]) * s1;

    #define DQ(b, sh, s, c) fmaf((float)(int)((((uint32_t)(b) >> (sh)) & 15u) ^ 8u), (s), (c))
    __half2 h0 = __floats2half2_rn(DQ(b00, 0, s0, c0), DQ(b00, 4, s0, c0));
    __half2 h1 = __floats2half2_rn(DQ(b01, 0, s0, c0), DQ(b01, 4, s0, c0));
    __half2 h2 = __floats2half2_rn(DQ(b10, 0, s1, c1), DQ(b10, 4, s1, c1));
    __half2 h3 = __floats2half2_rn(DQ(b11, 0, s1, c1), DQ(b11, 4, s1, c1));
    #undef DQ

    uint4 o;
    o.x = *(uint32_t*)&h0; o.y = *(uint32_t*)&h1;
    o.z = *(uint32_t*)&h2; o.w = *(uint32_t*)&h3;
    *(uint4*)(g_wd + (size_t)nt * TILE_HALVES
              + (size_t)(chunk * 4 + ks) * STEP_HALVES + np * 256 + lane * 8) = o;
}

// ============ main GEMM: smem-free, 64x64 warp tiles, nc-LDG streams, cs-stores ============
__global__ void __launch_bounds__(NTHREADS, 2)
gemm_kernel(float* __restrict__ y)
{
    const int tid  = threadIdx.x;
    const int lane = tid & 31;
    const int wid  = tid >> 5;
    const int warprow = wid >> 1;       // 0..1  (64 m)
    const int warpcol = wid & 1;        // 0..1  (64 n)
    const int mt = blockIdx.x;          // m fastest: co-resident CTAs share nt
    const int nt = blockIdx.y;

    // warp-private fragment streams (half-pointer arithmetic ONLY)
    const __half* Abase = g_xs + (size_t)mt * TILE_HALVES
                        + (size_t)(warprow * 4) * 256 + (size_t)lane * 8;
    const __half* Bbase = g_wd + (size_t)nt * TILE_HALVES
                        + (size_t)(warpcol * 4) * 256 + (size_t)lane * 8;

    float acc[4][8][4];
    #pragma unroll
    for (int mf = 0; mf < 4; mf++)
        #pragma unroll
        for (int f = 0; f < 8; f++)
            #pragma unroll
            for (int q = 0; q < 4; q++) acc[mf][f][q] = 0.0f;

    // parity ping-pong fragment buffers (proven mechanism)
    uint4 aEv[4], aOd[4], bEv[4], bOd[4];
    #pragma unroll
    for (int mf = 0; mf < 4; mf++) aEv[mf] = __ldg((const uint4*)(Abase + mf * 256));
    #pragma unroll
    for (int p = 0; p < 4; p++)    bEv[p]  = __ldg((const uint4*)(Bbase + p * 256));

    for (int s = 0; s < NSTEP; s += 2) {
        // ---- even step: compute from Ev, prefetch s+1 into Od ----
        {
            const __half* An = Abase + (size_t)(s + 1) * STEP_HALVES;
            const __half* Bn = Bbase + (size_t)(s + 1) * STEP_HALVES;
            #pragma unroll
            for (int mf = 0; mf < 4; mf++) aOd[mf] = __ldg((const uint4*)(An + mf * 256));
            #pragma unroll
            for (int p = 0; p < 4; p++)    bOd[p]  = __ldg((const uint4*)(Bn + p * 256));
        }
        #pragma unroll
        for (int mf = 0; mf < 4; mf++)
            #pragma unroll
            for (int p = 0; p < 4; p++) {
                mma16(acc[mf][2*p][0], acc[mf][2*p][1], acc[mf][2*p][2], acc[mf][2*p][3],
                      aEv[mf].x, aEv[mf].y, aEv[mf].z, aEv[mf].w,
                      bEv[p].x, bEv[p].y);
                mma16(acc[mf][2*p+1][0], acc[mf][2*p+1][1], acc[mf][2*p+1][2], acc[mf][2*p+1][3],
                      aEv[mf].x, aEv[mf].y, aEv[mf].z, aEv[mf].w,
                      bEv[p].z, bEv[p].w);
            }

        // ---- odd step: compute from Od, prefetch s+2 into Ev ----
        if (s + 2 < NSTEP) {
            const __half* An = Abase + (size_t)(s + 2) * STEP_HALVES;
            const __half* Bn = Bbase + (size_t)(s + 2) * STEP_HALVES;
            #pragma unroll
            for (int mf = 0; mf < 4; mf++) aEv[mf] = __ldg((const uint4*)(An + mf * 256));
            #pragma unroll
            for (int p = 0; p < 4; p++)    bEv[p]  = __ldg((const uint4*)(Bn + p * 256));
        }
        #pragma unroll
        for (int mf = 0; mf < 4; mf++)
            #pragma unroll
            for (int p = 0; p < 4; p++) {
                mma16(acc[mf][2*p][0], acc[mf][2*p][1], acc[mf][2*p][2], acc[mf][2*p][3],
                      aOd[mf].x, aOd[mf].y, aOd[mf].z, aOd[mf].w,
                      bOd[p].x, bOd[p].y);
                mma16(acc[mf][2*p+1][0], acc[mf][2*p+1][1], acc[mf][2*p+1][2], acc[mf][2*p+1][3],
                      aOd[mf].x, aOd[mf].y, aOd[mf].z, aOd[mf].w,
                      bOd[p].z, bOd[p].w);
            }
    }

    // ---- epilogue: streaming stores (y is write-once) keep B/x L2-resident ----
    const int g = lane >> 2, t = lane & 3;
    const int m0 = mt * BM, n0 = nt * BN;
    #pragma unroll
    for (int mf = 0; mf < 4; mf++) {
        const int row0 = m0 + warprow * 64 + mf * 16 + g;
        #pragma unroll
        for (int f = 0; f < 8; f++) {
            const int ncol = n0 + warpcol * 64 + (f >> 1) * 16 + (f & 1) * 8 + 2 * t;
            float* p0 = y + (size_t)row0 * OUT_F + ncol;
            float* p1 = p0 + (size_t)8 * OUT_F;
            stg_cs_v2(p0, acc[mf][f][0], acc[mf][f][1]);
            stg_cs_v2(p1, acc[mf][f][2], acc[mf][f][3]);
        }
    }
}

extern "C" void kernel_launch(void* const* d_in, const int* in_sizes, int n_in,
                              void* d_out, int out_size)
{
    const float* x  = (const float*)d_in[0];
    const int*   wp = (const int*)d_in[1];
    const float* ws = (const float*)d_in[2];
    const int*   wz = (const int*)d_in[3];
    float*       y  = (float*)d_out;

    prep_x_kernel<<<(TOKENS * (IN_F / 8)) / 256, 256>>>(x);
    prep_w_kernel<<<(OUT_F * (IN_F / 8)) / 256, 256>>>(wp, ws, wz);
    gemm_kernel<<<dim3(TOKENS / BM, OUT_F / BN), NTHREADS>>>(y);
}

// round 15
// speedup vs baseline: 4.2368x; 1.0139x over previous
#include <cuda_runtime.h>
#include <cuda_fp16.h>
#include <cstdint>

// ---------------- problem constants ----------------
#define TOKENS 4096
#define IN_F   4096
#define OUT_F  11008
#define NGRP   32

// ---------------- tile config ----------------
#define BM 128
#define BN 128
#define NSTEP (IN_F / 16)        // 256 k-steps of 16
#define STEP_HALVES 2048         // halves per (128-row, 16-k) fragment slab
#define TILE_HALVES ((size_t)NSTEP * STEP_HALVES)
#define NTHREADS 128             // 4 warps: 2x2 grid of 64x64 warp tiles

#define PREPX_BLOCKS 8192        // (TOKENS * IN_F/8) / 256
#define PREPW_BLOCKS 22016       // (OUT_F  * IN_F/8) / 256

// ---------------- persistent scratch ----------------
__device__ __half g_xs[(size_t)TOKENS * IN_F];    // x fp16, A-fragment-tiled
__device__ __half g_wd[(size_t)OUT_F * IN_F];     // W dequant fp16, B-fragment-tiled

__device__ __forceinline__ void mma16(float& d0, float& d1, float& d2, float& d3,
                                      uint32_t a0, uint32_t a1, uint32_t a2, uint32_t a3,
                                      uint32_t b0, uint32_t b1) {
    asm volatile("mma.sync.aligned.m16n8k16.row.col.f32.f16.f16.f32 "
                 "{%0,%1,%2,%3}, {%4,%5,%6,%7}, {%8,%9}, {%0,%1,%2,%3};"
                 : "+f"(d0), "+f"(d1), "+f"(d2), "+f"(d3)
                 : "r"(a0), "r"(a1), "r"(a2), "r"(a3), "r"(b0), "r"(b1));
}

__device__ __forceinline__ void stg_cs_v2(float* p, float a, float b) {
    asm volatile("st.global.cs.v2.f32 [%0], {%1, %2};" :: "l"(p), "f"(a), "f"(b) : "memory");
}

// ============ fused prepass: x -> fp16 A-tiling  |  W -> dequant fp16 B-tiling ============
// Output bytes identical to the R8/R11/R13/R14-passing prepasses.
__global__ void __launch_bounds__(256)
prep_fused_kernel(const float* __restrict__ x,
                  const int*   __restrict__ wp,
                  const float* __restrict__ ws,
                  const int*   __restrict__ wz)
{
    if (blockIdx.x < PREPX_BLOCKS) {
        const int gid  = blockIdx.x * 256 + threadIdx.x;
        const int lane = gid & 31;
        const int blk  = (gid >> 5) & 31;          // ks*8 + mb within 64-k chunk
        const int stg  = gid >> 10;                // mt*64 + chunk
        const int chunk = stg & 63;
        const int mt   = stg >> 6;
        const int ks = blk >> 3, mb = blk & 7;
        const int m = mt * 128 + mb * 16 + (lane >> 2);
        const int k = chunk * 64 + ks * 16 + (lane & 3) * 2;

        const float* xr = x + (size_t)m * IN_F + k;
        const float2 v0 = *(const float2*)(xr);
        const float2 v1 = *(const float2*)(xr + (size_t)8 * IN_F);
        const float2 v2 = *(const float2*)(xr + 8);
        const float2 v3 = *(const float2*)(xr + (size_t)8 * IN_F + 8);

        __half2 h0 = __floats2half2_rn(v0.x, v0.y);
        __half2 h1 = __floats2half2_rn(v1.x, v1.y);
        __half2 h2 = __floats2half2_rn(v2.x, v2.y);
        __half2 h3 = __floats2half2_rn(v3.x, v3.y);

        uint4 o;
        o.x = *(uint32_t*)&h0; o.y = *(uint32_t*)&h1;
        o.z = *(uint32_t*)&h2; o.w = *(uint32_t*)&h3;
        *(uint4*)(g_xs + (size_t)mt * TILE_HALVES
                  + (size_t)(chunk * 4 + ks) * STEP_HALVES + mb * 256 + lane * 8) = o;
    } else {
        const int gid  = (blockIdx.x - PREPX_BLOCKS) * 256 + threadIdx.x;
        const int lane = gid & 31;
        const int blk  = (gid >> 5) & 31;
        const int stg  = gid >> 10;                // nt*64 + chunk
        const int chunk = stg & 63;
        const int nt   = stg >> 6;
        const int ks = blk >> 3, np = blk & 7;
        const int n = nt * 128 + np * 16 + (lane >> 2);
        const int k = chunk * 64 + ks * 16 + (lane & 3) * 2;
        const int grp = k >> 7;

        const int* r0 = wp + (size_t)n * 2048;     // one packed byte per int32
        const int* r1 = r0 + (size_t)8 * 2048;
        const int i0 = k >> 1;
        const int b00 = r0[i0], b01 = r0[i0 + 4];
        const int b10 = r1[i0], b11 = r1[i0 + 4];

        const float s0 = ws[(size_t)n * NGRP + grp];
        const float c0 = (-8.0f - (float)wz[(size_t)n * NGRP + grp]) * s0;
        const float s1 = ws[(size_t)(n + 8) * NGRP + grp];
        const float c1 = (-8.0f - (float)wz[(size_t)(n + 8) * NGRP + grp]) * s1;

        #define DQ(b, sh, s, c) fmaf((float)(int)((((uint32_t)(b) >> (sh)) & 15u) ^ 8u), (s), (c))
        __half2 h0 = __floats2half2_rn(DQ(b00, 0, s0, c0), DQ(b00, 4, s0, c0));
        __half2 h1 = __floats2half2_rn(DQ(b01, 0, s0, c0), DQ(b01, 4, s0, c0));
        __half2 h2 = __floats2half2_rn(DQ(b10, 0, s1, c1), DQ(b10, 4, s1, c1));
        __half2 h3 = __floats2half2_rn(DQ(b11, 0, s1, c1), DQ(b11, 4, s1, c1));
        #undef DQ

        uint4 o;
        o.x = *(uint32_t*)&h0; o.y = *(uint32_t*)&h1;
        o.z = *(uint32_t*)&h2; o.w = *(uint32_t*)&h3;
        *(uint4*)(g_wd + (size_t)nt * TILE_HALVES
                  + (size_t)(chunk * 4 + ks) * STEP_HALVES + np * 256 + lane * 8) = o;
    }
}

// ============ main GEMM: smem-free, 64x64 warp tiles, direct-LDG streams ============
#define MMA_BURST(A, B)                                                              \
    _Pragma("unroll")                                                                \
    for (int mf = 0; mf < 4; mf++)                                                   \
        _Pragma("unroll")                                                            \
        for (int p = 0; p < 4; p++) {                                                \
            mma16(acc[mf][2*p][0], acc[mf][2*p][1], acc[mf][2*p][2], acc[mf][2*p][3],\
                  A[mf].x, A[mf].y, A[mf].z, A[mf].w, B[p].x, B[p].y);               \
            mma16(acc[mf][2*p+1][0], acc[mf][2*p+1][1],                              \
                  acc[mf][2*p+1][2], acc[mf][2*p+1][3],                              \
                  A[mf].x, A[mf].y, A[mf].z, A[mf].w, B[p].z, B[p].w);               \
        }

__global__ void __launch_bounds__(NTHREADS, 2)
gemm_kernel(float* __restrict__ y)
{
    const int tid  = threadIdx.x;
    const int lane = tid & 31;
    const int wid  = tid >> 5;
    const int warprow = wid >> 1;       // 0..1  (64 m)
    const int warpcol = wid & 1;        // 0..1  (64 n)
    const int mt = blockIdx.x;          // m fastest: co-resident CTAs share nt
    const int nt = blockIdx.y;

    const __half* Abase = g_xs + (size_t)mt * TILE_HALVES
                        + (size_t)(warprow * 4) * 256 + (size_t)lane * 8;
    const __half* Bbase = g_wd + (size_t)nt * TILE_HALVES
                        + (size_t)(warpcol * 4) * 256 + (size_t)lane * 8;

    float acc[4][8][4];
    #pragma unroll
    for (int mf = 0; mf < 4; mf++)
        #pragma unroll
        for (int f = 0; f < 8; f++)
            #pragma unroll
            for (int q = 0; q < 4; q++) acc[mf][f][q] = 0.0f;

    uint4 aEv[4], aOd[4], bEv[4], bOd[4];
    #pragma unroll
    for (int mf = 0; mf < 4; mf++) aEv[mf] = __ldg((const uint4*)(Abase + mf * 256));
    #pragma unroll
    for (int p = 0; p < 4; p++)    bEv[p]  = __ldg((const uint4*)(Bbase + p * 256));

    // steady state: no tail branch (runs s = 0 .. NSTEP-4 pairs)
    #pragma unroll 2
    for (int s = 0; s < NSTEP - 2; s += 2) {
        {
            const __half* An = Abase + (size_t)(s + 1) * STEP_HALVES;
            const __half* Bn = Bbase + (size_t)(s + 1) * STEP_HALVES;
            #pragma unroll
            for (int mf = 0; mf < 4; mf++) aOd[mf] = __ldg((const uint4*)(An + mf * 256));
            #pragma unroll
            for (int p = 0; p < 4; p++)    bOd[p]  = __ldg((const uint4*)(Bn + p * 256));
        }
        MMA_BURST(aEv, bEv)
        {
            const __half* An = Abase + (size_t)(s + 2) * STEP_HALVES;
            const __half* Bn = Bbase + (size_t)(s + 2) * STEP_HALVES;
            #pragma unroll
            for (int mf = 0; mf < 4; mf++) aEv[mf] = __ldg((const uint4*)(An + mf * 256));
            #pragma unroll
            for (int p = 0; p < 4; p++)    bEv[p]  = __ldg((const uint4*)(Bn + p * 256));
        }
        MMA_BURST(aOd, bOd)
    }

    // peeled final 2 steps (s = NSTEP-2, NSTEP-1)
    {
        const __half* An = Abase + (size_t)(NSTEP - 1) * STEP_HALVES;
        const __half* Bn = Bbase + (size_t)(NSTEP - 1) * STEP_HALVES;
        #pragma unroll
        for (int mf = 0; mf < 4; mf++) aOd[mf] = __ldg((const uint4*)(An + mf * 256));
        #pragma unroll
        for (int p = 0; p < 4; p++)    bOd[p]  = __ldg((const uint4*)(Bn + p * 256));
        MMA_BURST(aEv, bEv)
        MMA_BURST(aOd, bOd)
    }

    // ---- epilogue: streaming stores ----
    const int g = lane >> 2, t = lane & 3;
    const int m0 = mt * BM, n0 = nt * BN;
    #pragma unroll
    for (int mf = 0; mf < 4; mf++) {
        const int row0 = m0 + warprow * 64 + mf * 16 + g;
        #pragma unroll
        for (int f = 0; f < 8; f++) {
            const int ncol = n0 + warpcol * 64 + (f >> 1) * 16 + (f & 1) * 8 + 2 * t;
            float* p0 = y + (size_t)row0 * OUT_F + ncol;
            float* p1 = p0 + (size_t)8 * OUT_F;
            stg_cs_v2(p0, acc[mf][f][0], acc[mf][f][1]);
            stg_cs_v2(p1, acc[mf][f][2], acc[mf][f][3]);
        }
    }
}

extern "C" void kernel_launch(void* const* d_in, const int* in_sizes, int n_in,
                              void* d_out, int out_size)
{
    const float* x  = (const float*)d_in[0];
    const int*   wp = (const int*)d_in[1];
    const float* ws = (const float*)d_in[2];
    const int*   wz = (const int*)d_in[3];
    float*       y  = (float*)d_out;

    prep_fused_kernel<<<PREPX_BLOCKS + PREPW_BLOCKS, 256>>>(x, wp, ws, wz);
    gemm_kernel<<<dim3(TOKENS / BM, OUT_F / BN), NTHREADS>>>(y);
}

// round 16
// speedup vs baseline: 4.5722x; 1.0792x over previous
#include <cuda_runtime.h>
#include <cuda_fp16.h>
#include <cstdint>

// ---------------- problem constants ----------------
#define TOKENS 4096
#define IN_F   4096
#define OUT_F  11008
#define NGRP   32

// ---------------- tile config ----------------
#define BM 128
#define BN 64                    // CTA tile 128x64
#define NSTEP (IN_F / 16)        // 256 k-steps of 16
#define STEP_HALVES 2048         // halves per (128-row, 16-k) fragment slab
#define TILE_HALVES ((size_t)NSTEP * STEP_HALVES)
#define NTHREADS 128             // 4 warps: 2x2 grid of 64x32 warp tiles

#define PREPX_BLOCKS 8192        // (TOKENS * IN_F/8) / 256
#define PREPW_BLOCKS 22016       // (OUT_F  * IN_F/8) / 256

// ---------------- persistent scratch ----------------
__device__ __half g_xs[(size_t)TOKENS * IN_F];    // x fp16, A-fragment-tiled
__device__ __half g_wd[(size_t)OUT_F * IN_F];     // W dequant fp16, B-fragment-tiled

__device__ __forceinline__ void mma16(float& d0, float& d1, float& d2, float& d3,
                                      uint32_t a0, uint32_t a1, uint32_t a2, uint32_t a3,
                                      uint32_t b0, uint32_t b1) {
    asm volatile("mma.sync.aligned.m16n8k16.row.col.f32.f16.f16.f32 "
                 "{%0,%1,%2,%3}, {%4,%5,%6,%7}, {%8,%9}, {%0,%1,%2,%3};"
                 : "+f"(d0), "+f"(d1), "+f"(d2), "+f"(d3)
                 : "r"(a0), "r"(a1), "r"(a2), "r"(a3), "r"(b0), "r"(b1));
}

__device__ __forceinline__ void stg_cs_v2(float* p, float a, float b) {
    asm volatile("st.global.cs.v2.f32 [%0], {%1, %2};" :: "l"(p), "f"(a), "f"(b) : "memory");
}

// ============ fused prepass (byte-identical outputs to R8..R15 passing versions) ============
__global__ void __launch_bounds__(256)
prep_fused_kernel(const float* __restrict__ x,
                  const int*   __restrict__ wp,
                  const float* __restrict__ ws,
                  const int*   __restrict__ wz)
{
    if (blockIdx.x < PREPX_BLOCKS) {
        const int gid  = blockIdx.x * 256 + threadIdx.x;
        const int lane = gid & 31;
        const int blk  = (gid >> 5) & 31;          // ks*8 + mb within 64-k chunk
        const int stg  = gid >> 10;                // mt*64 + chunk
        const int chunk = stg & 63;
        const int mt   = stg >> 6;
        const int ks = blk >> 3, mb = blk & 7;
        const int m = mt * 128 + mb * 16 + (lane >> 2);
        const int k = chunk * 64 + ks * 16 + (lane & 3) * 2;

        const float* xr = x + (size_t)m * IN_F + k;
        const float2 v0 = *(const float2*)(xr);
        const float2 v1 = *(const float2*)(xr + (size_t)8 * IN_F);
        const float2 v2 = *(const float2*)(xr + 8);
        const float2 v3 = *(const float2*)(xr + (size_t)8 * IN_F + 8);

        __half2 h0 = __floats2half2_rn(v0.x, v0.y);
        __half2 h1 = __floats2half2_rn(v1.x, v1.y);
        __half2 h2 = __floats2half2_rn(v2.x, v2.y);
        __half2 h3 = __floats2half2_rn(v3.x, v3.y);

        uint4 o;
        o.x = *(uint32_t*)&h0; o.y = *(uint32_t*)&h1;
        o.z = *(uint32_t*)&h2; o.w = *(uint32_t*)&h3;
        *(uint4*)(g_xs + (size_t)mt * TILE_HALVES
                  + (size_t)(chunk * 4 + ks) * STEP_HALVES + mb * 256 + lane * 8) = o;
    } else {
        const int gid  = (blockIdx.x - PREPX_BLOCKS) * 256 + threadIdx.x;
        const int lane = gid & 31;
        const int blk  = (gid >> 5) & 31;
        const int stg  = gid >> 10;                // nt128*64 + chunk
        const int chunk = stg & 63;
        const int nt   = stg >> 6;
        const int ks = blk >> 3, np = blk & 7;
        const int n = nt * 128 + np * 16 + (lane >> 2);
        const int k = chunk * 64 + ks * 16 + (lane & 3) * 2;
        const int grp = k >> 7;

        const int* r0 = wp + (size_t)n * 2048;     // one packed byte per int32
        const int* r1 = r0 + (size_t)8 * 2048;
        const int i0 = k >> 1;
        const int b00 = r0[i0], b01 = r0[i0 + 4];
        const int b10 = r1[i0], b11 = r1[i0 + 4];

        const float s0 = ws[(size_t)n * NGRP + grp];
        const float c0 = (-8.0f - (float)wz[(size_t)n * NGRP + grp]) * s0;
        const float s1 = ws[(size_t)(n + 8) * NGRP + grp];
        const float c1 = (-8.0f - (float)wz[(size_t)(n + 8) * NGRP + grp]) * s1;

        #define DQ(b, sh, s, c) fmaf((float)(int)((((uint32_t)(b) >> (sh)) & 15u) ^ 8u), (s), (c))
        __half2 h0 = __floats2half2_rn(DQ(b00, 0, s0, c0), DQ(b00, 4, s0, c0));
        __half2 h1 = __floats2half2_rn(DQ(b01, 0, s0, c0), DQ(b01, 4, s0, c0));
        __half2 h2 = __floats2half2_rn(DQ(b10, 0, s1, c1), DQ(b10, 4, s1, c1));
        __half2 h3 = __floats2half2_rn(DQ(b11, 0, s1, c1), DQ(b11, 4, s1, c1));
        #undef DQ

        uint4 o;
        o.x = *(uint32_t*)&h0; o.y = *(uint32_t*)&h1;
        o.z = *(uint32_t*)&h2; o.w = *(uint32_t*)&h3;
        *(uint4*)(g_wd + (size_t)nt * TILE_HALVES
                  + (size_t)(chunk * 4 + ks) * STEP_HALVES + np * 256 + lane * 8) = o;
    }
}

// ============ main GEMM: 128x64 CTA, 64x32 warp tiles, smem-free LDG streams ============
#define MMA_BURST(A, B)                                                              \
    _Pragma("unroll")                                                                \
    for (int mf = 0; mf < 4; mf++)                                                   \
        _Pragma("unroll")                                                            \
        for (int p = 0; p < 2; p++) {                                                \
            mma16(acc[mf][2*p][0], acc[mf][2*p][1], acc[mf][2*p][2], acc[mf][2*p][3],\
                  A[mf].x, A[mf].y, A[mf].z, A[mf].w, B[p].x, B[p].y);               \
            mma16(acc[mf][2*p+1][0], acc[mf][2*p+1][1],                              \
                  acc[mf][2*p+1][2], acc[mf][2*p+1][3],                              \
                  A[mf].x, A[mf].y, A[mf].z, A[mf].w, B[p].z, B[p].w);               \
        }

__global__ void __launch_bounds__(NTHREADS, 3)
gemm_kernel(float* __restrict__ y)
{
    const int tid  = threadIdx.x;
    const int lane = tid & 31;
    const int wid  = tid >> 5;
    const int warprow = wid >> 1;       // 0..1  (64 m)
    const int warpcol = wid & 1;        // 0..1  (32 n)
    const int mt = blockIdx.x;          // 0..31, fastest: co-resident CTAs share nt
    const int nt = blockIdx.y;          // 0..171 (64-wide n tiles)

    const __half* Abase = g_xs + (size_t)mt * TILE_HALVES
                        + (size_t)(warprow * 4) * 256 + (size_t)lane * 8;
    const __half* Bbase = g_wd + (size_t)(nt >> 1) * TILE_HALVES
                        + (size_t)(((nt & 1) * 4 + warpcol * 2)) * 256 + (size_t)lane * 8;

    float acc[4][4][4];
    #pragma unroll
    for (int mf = 0; mf < 4; mf++)
        #pragma unroll
        for (int f = 0; f < 4; f++)
            #pragma unroll
            for (int q = 0; q < 4; q++) acc[mf][f][q] = 0.0f;

    uint4 aEv[4], aOd[4], bEv[2], bOd[2];
    #pragma unroll
    for (int mf = 0; mf < 4; mf++) aEv[mf] = __ldg((const uint4*)(Abase + mf * 256));
    #pragma unroll
    for (int p = 0; p < 2; p++)    bEv[p]  = __ldg((const uint4*)(Bbase + p * 256));

    // steady state (no tail branch)
    #pragma unroll 2
    for (int s = 0; s < NSTEP - 2; s += 2) {
        {
            const __half* An = Abase + (size_t)(s + 1) * STEP_HALVES;
            const __half* Bn = Bbase + (size_t)(s + 1) * STEP_HALVES;
            #pragma unroll
            for (int mf = 0; mf < 4; mf++) aOd[mf] = __ldg((const uint4*)(An + mf * 256));
            #pragma unroll
            for (int p = 0; p < 2; p++)    bOd[p]  = __ldg((const uint4*)(Bn + p * 256));
        }
        MMA_BURST(aEv, bEv)
        {
            const __half* An = Abase + (size_t)(s + 2) * STEP_HALVES;
            const __half* Bn = Bbase + (size_t)(s + 2) * STEP_HALVES;
            #pragma unroll
            for (int mf = 0; mf < 4; mf++) aEv[mf] = __ldg((const uint4*)(An + mf * 256));
            #pragma unroll
            for (int p = 0; p < 2; p++)    bEv[p]  = __ldg((const uint4*)(Bn + p * 256));
        }
        MMA_BURST(aOd, bOd)
    }

    // peeled final 2 steps
    {
        const __half* An = Abase + (size_t)(NSTEP - 1) * STEP_HALVES;
        const __half* Bn = Bbase + (size_t)(NSTEP - 1) * STEP_HALVES;
        #pragma unroll
        for (int mf = 0; mf < 4; mf++) aOd[mf] = __ldg((const uint4*)(An + mf * 256));
        #pragma unroll
        for (int p = 0; p < 2; p++)    bOd[p]  = __ldg((const uint4*)(Bn + p * 256));
        MMA_BURST(aEv, bEv)
        MMA_BURST(aOd, bOd)
    }

    // ---- epilogue: streaming stores ----
    const int g = lane >> 2, t = lane & 3;
    const int m0 = mt * BM, n0 = nt * BN;
    #pragma unroll
    for (int mf = 0; mf < 4; mf++) {
        const int row0 = m0 + warprow * 64 + mf * 16 + g;
        #pragma unroll
        for (int f = 0; f < 4; f++) {
            // f = 2*p + o: n-pair p (16 n), within-pair o (8 n)
            const int ncol = n0 + warpcol * 32 + (f >> 1) * 16 + (f & 1) * 8 + 2 * t;
            float* p0 = y + (size_t)row0 * OUT_F + ncol;
            float* p1 = p0 + (size_t)8 * OUT_F;
            stg_cs_v2(p0, acc[mf][f][0], acc[mf][f][1]);
            stg_cs_v2(p1, acc[mf][f][2], acc[mf][f][3]);
        }
    }
}

extern "C" void kernel_launch(void* const* d_in, const int* in_sizes, int n_in,
                              void* d_out, int out_size)
{
    const float* x  = (const float*)d_in[0];
    const int*   wp = (const int*)d_in[1];
    const float* ws = (const float*)d_in[2];
    const int*   wz = (const int*)d_in[3];
    float*       y  = (float*)d_out;

    prep_fused_kernel<<<PREPX_BLOCKS + PREPW_BLOCKS, 256>>>(x, wp, ws, wz);
    gemm_kernel<<<dim3(TOKENS / BM, OUT_F / BN), NTHREADS>>>(y);
}